// round 3
// baseline (speedup 1.0000x reference)
#include <cuda_runtime.h>
#include <math.h>

// ---------------- problem constants ----------------
#define BB     8
#define NQT    350
#define NP     300
#define NT     50
#define DIM    256
#define HH     8
#define DH     32
#define NLVL   4
#define NPNT   4
#define NLAY   6
#define NH2    2
#define DH2    128
#define DFF    1024
#define STOT   20197

// output layout (tuple flattened in order)
#define OUT_PROP   0            // 8*300*256  = 614400
#define OUT_PREF   614400       // 8*300*4    = 9600
#define OUT_PTCOS  624000       // 8*2*300*50 = 240000
#define OUT_PPCOS  864000       // 8*2*300*300= 1440000
#define OUT_PTMM   2304000
#define OUT_PPMM   2544000

__device__ __constant__ int c_hl[4]    = {100, 50, 25, 13};
__device__ __constant__ int c_wl[4]    = {152, 76, 38, 19};
__device__ __constant__ int c_start[4] = {0, 15200, 19000, 19950};

// ---------------- scratch (device globals, no allocation) ----------------
__device__ float g_value[(size_t)BB * STOT * DIM];   // 41,363,456 floats
__device__ float g_prop [BB * NP * DIM];
__device__ float g_ppos [BB * NP * DIM];
__device__ float g_q    [BB * NP * DIM];
__device__ float g_off  [BB * NP * 256];
__device__ float g_alog [BB * NP * 128];
__device__ float g_attn [BB * NP * 128];
__device__ float g_capre[BB * NP * DIM];
__device__ float g_ca   [BB * NP * DIM];
__device__ float g_ffn  [BB * NP * DFF];
__device__ float g_track[BB * NT * DIM];
__device__ float g_qh   [BB * NP * DIM];
__device__ float g_kp   [BB * NP * DIM];
__device__ float g_kt   [BB * NT * DIM];
__device__ float g_qn   [BB * NP * NH2];
__device__ float g_kpn  [BB * NP * NH2];
__device__ float g_ktn  [BB * NT * NH2];

// ---------------- generic tiled SGEMM:  C = A(MxK) @ B(KxN) + bias, opt ReLU ----------------
// 64x64 tile, BK=16, 256 threads, 4x4 register micro-tile.
template <bool RELU>
__global__ void sgemm_kernel(const float* __restrict__ A, const float* __restrict__ Bm,
                             const float* __restrict__ bias, float* __restrict__ C,
                             int M, int N, int K) {
    __shared__ float As[16][65];
    __shared__ float Bs[16][64];
    const int tid = threadIdx.x;
    const int tx = tid & 15, ty = tid >> 4;
    const int bm = blockIdx.x, bn = blockIdx.y;

    float acc[4][4] = {};

    const int ar = tid >> 2, ac = (tid & 3) * 4;     // A tile load: 64 rows x 16 cols
    const int br = tid >> 4, bc = (tid & 15) * 4;    // B tile load: 16 rows x 64 cols
    const int arow = bm * 64 + ar;
    const float* Aptr = A + (size_t)arow * K + ac;
    const float* Bptr = Bm + (size_t)br * N + bn * 64 + bc;

    for (int kt = 0; kt < K; kt += 16) {
        float4 av = make_float4(0.f, 0.f, 0.f, 0.f);
        if (arow < M) av = *(const float4*)(Aptr + kt);
        As[ac + 0][ar] = av.x; As[ac + 1][ar] = av.y;
        As[ac + 2][ar] = av.z; As[ac + 3][ar] = av.w;
        float4 bv = *(const float4*)(Bptr + (size_t)kt * N);
        *(float4*)&Bs[br][bc] = bv;
        __syncthreads();
        #pragma unroll
        for (int k = 0; k < 16; k++) {
            float a0 = As[k][ty * 4 + 0], a1 = As[k][ty * 4 + 1];
            float a2 = As[k][ty * 4 + 2], a3 = As[k][ty * 4 + 3];
            float b0 = Bs[k][tx * 4 + 0], b1 = Bs[k][tx * 4 + 1];
            float b2 = Bs[k][tx * 4 + 2], b3 = Bs[k][tx * 4 + 3];
            acc[0][0] += a0 * b0; acc[0][1] += a0 * b1; acc[0][2] += a0 * b2; acc[0][3] += a0 * b3;
            acc[1][0] += a1 * b0; acc[1][1] += a1 * b1; acc[1][2] += a1 * b2; acc[1][3] += a1 * b3;
            acc[2][0] += a2 * b0; acc[2][1] += a2 * b1; acc[2][2] += a2 * b2; acc[2][3] += a2 * b3;
            acc[3][0] += a3 * b0; acc[3][1] += a3 * b1; acc[3][2] += a3 * b2; acc[3][3] += a3 * b3;
        }
        __syncthreads();
    }
    #pragma unroll
    for (int i = 0; i < 4; i++) {
        int row = bm * 64 + ty * 4 + i;
        if (row < M) {
            #pragma unroll
            for (int j = 0; j < 4; j++) {
                int col = bn * 64 + tx * 4 + j;
                float v = acc[i][j] + bias[col];
                if (RELU) v = fmaxf(v, 0.f);
                C[(size_t)row * N + col] = v;
            }
        }
    }
}

// ---------------- misc kernels ----------------
__global__ void posemb_kernel(const float* __restrict__ refp, float* __restrict__ out) {
    int idx = blockIdx.x * blockDim.x + threadIdx.x;
    if (idx >= BB * NP * DIM) return;
    int d = idx & 255;
    int q = (idx >> 8) % NP;
    int b = idx / (256 * NP);
    int c = d >> 6;            // which coord (0..3)
    int r = d & 63;
    int j = r >> 1;
    float pos = refp[(b * NQT + q) * 4 + c];
    float t = powf(10000.0f, (float)j / 32.0f);
    float arg = pos * 6.2831853071795864f / t;
    out[idx] = (r & 1) ? cosf(arg) : sinf(arg);
}

__global__ void copy_rows_kernel(const float* __restrict__ src, float* __restrict__ dst,
                                 int rowoff, int nrows) {
    int idx = blockIdx.x * blockDim.x + threadIdx.x;
    int total = BB * nrows * DIM;
    if (idx >= total) return;
    int d = idx & 255;
    int r = (idx >> 8) % nrows;
    int b = idx / (256 * nrows);
    dst[idx] = src[((size_t)(b * NQT + rowoff + r)) * DIM + d];
}

__global__ void add_kernel(const float* __restrict__ a, const float* __restrict__ b,
                           float* __restrict__ o, int n) {
    int idx = blockIdx.x * blockDim.x + threadIdx.x;
    if (idx < n) o[idx] = a[idx] + b[idx];
}

__global__ void attn_softmax_kernel() {
    int idx = blockIdx.x * blockDim.x + threadIdx.x;   // BB*NP*HH
    if (idx >= BB * NP * HH) return;
    int h = idx & 7;
    int bq = idx >> 3;
    const float* in = g_alog + (size_t)bq * 128 + h * 16;
    float mx = -1e30f;
    #pragma unroll
    for (int j = 0; j < 16; j++) mx = fmaxf(mx, in[j]);
    float e[16], s = 0.f;
    #pragma unroll
    for (int j = 0; j < 16; j++) { e[j] = expf(in[j] - mx); s += e[j]; }
    float inv = 1.0f / s;
    float* o = g_attn + (size_t)bq * 128 + h * 16;
    #pragma unroll
    for (int j = 0; j < 16; j++) o[j] = e[j] * inv;
}

// bilinear gather + attention-weighted sum.  block = (b,q), warp = head, lane = channel
__global__ void gather_kernel(const float* __restrict__ refp) {
    int bq = blockIdx.x;
    int b = bq / NP, q = bq % NP;
    int h = threadIdx.x >> 5;
    int lane = threadIdx.x & 31;
    const float* r = refp + (size_t)(b * NQT + q) * 4;
    float rx = r[0], ry = r[1], rw = r[2], rh = r[3];
    const float* offp = g_off + (size_t)bq * 256;
    const float* attp = g_attn + (size_t)bq * 128;
    float acc = 0.f;
    #pragma unroll
    for (int l = 0; l < 4; l++) {
        int wl = c_wl[l], hl = c_hl[l], st = c_start[l];
        float wlf = (float)wl, hlf = (float)hl;
        const float* vbase = g_value + ((size_t)(b * STOT + st) * HH + h) * DH + lane;
        #pragma unroll
        for (int p = 0; p < 4; p++) {
            int oi = ((h * 4 + l) * 4 + p) * 2;
            float ox = offp[oi], oy = offp[oi + 1];
            float a = attp[h * 16 + l * 4 + p];
            float locx = rx + ox * 0.125f * rw;   // off/P * w * 0.5
            float locy = ry + oy * 0.125f * rh;
            float x = locx * wlf - 0.5f, y = locy * hlf - 0.5f;
            float x0 = floorf(x), y0 = floorf(y);
            float lx = x - x0, ly = y - y0;
            float wgt[4] = { (1.f - lx) * (1.f - ly), lx * (1.f - ly),
                             (1.f - lx) * ly,         lx * ly };
            float xs[4] = { x0, x0 + 1.f, x0, x0 + 1.f };
            float ys[4] = { y0, y0, y0 + 1.f, y0 + 1.f };
            #pragma unroll
            for (int c = 0; c < 4; c++) {
                float xi = xs[c], yi = ys[c];
                if (xi >= 0.f && xi <= wlf - 1.f && yi >= 0.f && yi <= hlf - 1.f) {
                    int xii = (int)xi, yii = (int)yi;
                    float v = vbase[(size_t)(yii * wl + xii) * (HH * DH)];
                    acc += a * wgt[c] * v;
                }
            }
        }
    }
    g_capre[(size_t)bq * DIM + h * DH + lane] = acc;
}

// fused residual + layernorm (warp per row, in-place on g_prop)
__global__ void ln_kernel(const float* __restrict__ addv, const float* __restrict__ w,
                          const float* __restrict__ bia) {
    int row = blockIdx.x * 8 + (threadIdx.x >> 5);
    int lane = threadIdx.x & 31;
    if (row >= BB * NP) return;
    float x[8];
    float s = 0.f;
    #pragma unroll
    for (int i = 0; i < 8; i++) {
        int d = lane + 32 * i;
        x[i] = g_prop[(size_t)row * DIM + d] + addv[(size_t)row * DIM + d];
        s += x[i];
    }
    #pragma unroll
    for (int o = 16; o > 0; o >>= 1) s += __shfl_xor_sync(0xffffffff, s, o);
    float m = s / 256.0f;
    float v = 0.f;
    #pragma unroll
    for (int i = 0; i < 8; i++) { float dd = x[i] - m; v += dd * dd; }
    #pragma unroll
    for (int o = 16; o > 0; o >>= 1) v += __shfl_xor_sync(0xffffffff, v, o);
    v /= 256.0f;
    float inv = rsqrtf(v + 1e-5f);
    #pragma unroll
    for (int i = 0; i < 8; i++) {
        int d = lane + 32 * i;
        g_prop[(size_t)row * DIM + d] = (x[i] - m) * inv * w[d] + bia[d];
    }
}

// per (row, h2) L2 norm of a 128-dim half-row
__global__ void norm_kernel(const float* __restrict__ X, int rows, float* __restrict__ out) {
    int idx = blockIdx.x * blockDim.x + threadIdx.x;
    if (idx >= rows * NH2) return;
    int h = idx & 1, r = idx >> 1;
    const float* x = X + (size_t)r * DIM + h * DH2;
    float s = 0.f;
    #pragma unroll 8
    for (int d = 0; d < 128; d++) { float v = x[d]; s += v * v; }
    out[idx] = sqrtf(s);
}

// fused weight_attn:   dots + softmax(mm) + cosine.  grid = (NP, 2, B), 128 threads.
__global__ void wattn_kernel(const float* __restrict__ Q, const float* __restrict__ K,
                             const float* __restrict__ qn, const float* __restrict__ kn,
                             int nk, float* __restrict__ cos_out, float* __restrict__ mm_out) {
    int qi = blockIdx.x, h = blockIdx.y, b = blockIdx.z;
    __shared__ float qv[128];
    __shared__ float sc[304];
    __shared__ float red[128];
    int t = threadIdx.x;
    int qrow = b * NP + qi;
    qv[t] = Q[(size_t)qrow * DIM + h * DH2 + t];
    __syncthreads();
    for (int k = t; k < nk; k += 128) {
        const float* kr = K + ((size_t)(b * nk + k)) * DIM + h * DH2;
        float dot = 0.f;
        #pragma unroll 8
        for (int d = 0; d < 128; d++) dot += qv[d] * kr[d];
        sc[k] = dot;
    }
    __syncthreads();
    const float scale = 0.088388347648318447f;   // 1/sqrt(128)
    float mx = -1e30f;
    for (int k = t; k < nk; k += 128) mx = fmaxf(mx, sc[k] * scale);
    red[t] = mx; __syncthreads();
    for (int s = 64; s > 0; s >>= 1) { if (t < s) red[t] = fmaxf(red[t], red[t + s]); __syncthreads(); }
    mx = red[0]; __syncthreads();
    float sum = 0.f;
    for (int k = t; k < nk; k += 128) sum += expf(sc[k] * scale - mx);
    red[t] = sum; __syncthreads();
    for (int s = 64; s > 0; s >>= 1) { if (t < s) red[t] += red[t + s]; __syncthreads(); }
    sum = red[0];
    float inv = 1.0f / sum;
    float qnv = qn[qrow * NH2 + h] + 1e-6f;
    size_t base = ((size_t)(b * NH2 + h) * NP + qi) * nk;
    for (int k = t; k < nk; k += 128) {
        mm_out[base + k] = expf(sc[k] * scale - mx) * inv;
        float knv = kn[(b * nk + k) * NH2 + h] + 1e-6f;
        cos_out[base + k] = sc[k] / (qnv * knv);
    }
}

__global__ void copy_prop_out(float* __restrict__ out) {
    int idx = blockIdx.x * blockDim.x + threadIdx.x;
    if (idx < BB * NP * DIM) out[OUT_PROP + idx] = g_prop[idx];
}
__global__ void copy_pref_out(const float* __restrict__ refp, float* __restrict__ out) {
    int idx = blockIdx.x * blockDim.x + threadIdx.x;
    if (idx >= BB * NP * 4) return;
    int c = idx & 3;
    int q = (idx >> 2) % NP;
    int b = idx / (4 * NP);
    out[OUT_PREF + idx] = refp[((size_t)(b * NQT + q)) * 4 + c];
}

// ---------------- host orchestration ----------------
static inline int cdiv(int a, int b) { return (a + b - 1) / b; }

extern "C" void kernel_launch(void* const* d_in, const int* in_sizes, int n_in,
                              void* d_out, int out_size) {
    const float* tgt   = (const float*)d_in[0];
    const float* refp  = (const float*)d_in[1];
    const float* src   = (const float*)d_in[2];
    const float* Woff  = (const float*)d_in[7];
    const float* boff  = (const float*)d_in[8];
    const float* Wa    = (const float*)d_in[9];
    const float* ba    = (const float*)d_in[10];
    const float* Wv    = (const float*)d_in[11];
    const float* bv    = (const float*)d_in[12];
    const float* Wout  = (const float*)d_in[13];
    const float* bout  = (const float*)d_in[14];
    const float* Wl1   = (const float*)d_in[15];
    const float* bl1   = (const float*)d_in[16];
    const float* Wl2   = (const float*)d_in[17];
    const float* bl2   = (const float*)d_in[18];
    const float* Wq    = (const float*)d_in[19];
    const float* bq    = (const float*)d_in[20];
    const float* Wk    = (const float*)d_in[21];
    const float* bk    = (const float*)d_in[22];
    const float* n1w   = (const float*)d_in[23];
    const float* n1b   = (const float*)d_in[24];
    const float* n3w   = (const float*)d_in[25];
    const float* n3b   = (const float*)d_in[26];
    float* out = (float*)d_out;

    // device addresses of scratch globals
    float *pv, *pprop, *pppos, *pq, *poff, *palog, *pcapre, *pca, *pffn, *ptrack;
    float *pqh, *pkp, *pkt, *pqn, *pkpn, *pktn;
    cudaGetSymbolAddress((void**)&pv,     g_value);
    cudaGetSymbolAddress((void**)&pprop,  g_prop);
    cudaGetSymbolAddress((void**)&pppos,  g_ppos);
    cudaGetSymbolAddress((void**)&pq,     g_q);
    cudaGetSymbolAddress((void**)&poff,   g_off);
    cudaGetSymbolAddress((void**)&palog,  g_alog);
    cudaGetSymbolAddress((void**)&pcapre, g_capre);
    cudaGetSymbolAddress((void**)&pca,    g_ca);
    cudaGetSymbolAddress((void**)&pffn,   g_ffn);
    cudaGetSymbolAddress((void**)&ptrack, g_track);
    cudaGetSymbolAddress((void**)&pqh,    g_qh);
    cudaGetSymbolAddress((void**)&pkp,    g_kp);
    cudaGetSymbolAddress((void**)&pkt,    g_kt);
    cudaGetSymbolAddress((void**)&pqn,    g_qn);
    cudaGetSymbolAddress((void**)&pkpn,   g_kpn);
    cudaGetSymbolAddress((void**)&pktn,   g_ktn);

    auto gemm = [&](const float* A, const float* Bw, const float* bias, float* C,
                    int M, int N, int K, bool relu) {
        dim3 g(cdiv(M, 64), N / 64);
        if (relu) sgemm_kernel<true><<<g, 256>>>(A, Bw, bias, C, M, N, K);
        else      sgemm_kernel<false><<<g, 256>>>(A, Bw, bias, C, M, N, K);
    };

    const int NPROPS = BB * NP;        // 2400 proposal rows
    const int NEL = NPROPS * DIM;      // 614400

    // init: split tgt, positional embedding
    copy_rows_kernel<<<cdiv(NEL, 256), 256>>>(tgt, pprop, 0, NP);
    copy_rows_kernel<<<cdiv(BB * NT * DIM, 256), 256>>>(tgt, ptrack, NP, NT);
    posemb_kernel<<<cdiv(NEL, 256), 256>>>(refp, pppos);

    const int MV = BB * STOT;          // 161576 value rows

    for (int l = 0; l < NLAY; l++) {
        // q = proposals + pos
        add_kernel<<<cdiv(NEL, 256), 256>>>(pprop, pppos, pq, NEL);
        // value projection (the big one)
        gemm(src, Wv + (size_t)l * DIM * DIM, bv + l * DIM, pv, MV, DIM, DIM, false);
        // offsets + attention logits
        gemm(pq, Woff + (size_t)l * DIM * 256, boff + l * 256, poff, NPROPS, 256, DIM, false);
        gemm(pq, Wa + (size_t)l * DIM * 128, ba + l * 128, palog, NPROPS, 128, DIM, false);
        attn_softmax_kernel<<<cdiv(BB * NP * HH, 256), 256>>>();
        // deformable gather
        gather_kernel<<<BB * NP, 256>>>(refp);
        // output projection
        gemm(pcapre, Wout + (size_t)l * DIM * DIM, bout + l * DIM, pca, NPROPS, DIM, DIM, false);
        // residual + LN1
        ln_kernel<<<cdiv(NPROPS, 8), 256>>>(pca, n1w + l * DIM, n1b + l * DIM);
        // FFN
        gemm(pprop, Wl1 + (size_t)l * DIM * DFF, bl1 + l * DFF, pffn, NPROPS, DFF, DIM, true);
        gemm(pffn, Wl2 + (size_t)l * DFF * DIM, bl2 + l * DIM, pca, NPROPS, DIM, DFF, false);
        // residual + LN3
        ln_kernel<<<cdiv(NPROPS, 8), 256>>>(pca, n3w + l * DIM, n3b + l * DIM);
    }

    // weight_attn only matters for the last layer's weights
    const int L = NLAY - 1;
    gemm(pprop,  Wq + (size_t)L * DIM * DIM, bq + L * DIM, pqh, NPROPS, DIM, DIM, false);
    gemm(pprop,  Wk + (size_t)L * DIM * DIM, bk + L * DIM, pkp, NPROPS, DIM, DIM, false);
    gemm(ptrack, Wk + (size_t)L * DIM * DIM, bk + L * DIM, pkt, BB * NT, DIM, DIM, false);
    norm_kernel<<<cdiv(NPROPS * NH2, 256), 256>>>(pqh, NPROPS, pqn);
    norm_kernel<<<cdiv(NPROPS * NH2, 256), 256>>>(pkp, NPROPS, pkpn);
    norm_kernel<<<cdiv(BB * NT * NH2, 256), 256>>>(pkt, BB * NT, pktn);

    dim3 wg(NP, NH2, BB);
    wattn_kernel<<<wg, 128>>>(pqh, pkt, pqn, pktn, NT, out + OUT_PTCOS, out + OUT_PTMM);
    wattn_kernel<<<wg, 128>>>(pqh, pkp, pqn, pkpn, NP, out + OUT_PPCOS, out + OUT_PPMM);

    copy_prop_out<<<cdiv(NEL, 256), 256>>>(out);
    copy_pref_out<<<cdiv(BB * NP * 4, 256), 256>>>(refp, out);
}

// round 5
// speedup vs baseline: 2.2738x; 2.2738x over previous
#include <cuda_runtime.h>
#include <math.h>

// ---------------- problem constants ----------------
#define BB     8
#define NQT    350
#define NP     300
#define NT     50
#define DIM    256
#define HH     8
#define DH     32
#define NLVL   4
#define NPNT   4
#define NLAY   6
#define NH2    2
#define DH2    128
#define DFF    1024
#define STOT   20197

// output layout (tuple flattened in order)
#define OUT_PROP   0            // 8*300*256  = 614400
#define OUT_PREF   614400       // 8*300*4    = 9600
#define OUT_PTCOS  624000       // 8*2*300*50 = 240000
#define OUT_PPCOS  864000       // 8*2*300*300= 1440000
#define OUT_PTMM   2304000
#define OUT_PPMM   2544000

__device__ __constant__ int c_hl[4]    = {100, 50, 25, 13};
__device__ __constant__ int c_wl[4]    = {152, 76, 38, 19};
__device__ __constant__ int c_start[4] = {0, 15200, 19000, 19950};

// ---------------- scratch (device globals, no allocation) ----------------
__device__ float g_prop [BB * NP * DIM];
__device__ float g_ppos [BB * NP * DIM];
__device__ float g_q    [BB * NP * DIM];
__device__ float g_off  [BB * NP * 256];
__device__ float g_alog [BB * NP * 128];
__device__ float g_attn [BB * NP * 128];
__device__ float g_agg  [(size_t)BB * NP * HH * DIM];   // 4.9M floats
__device__ float g_coef [BB * NP * HH];
__device__ float g_capre[BB * NP * DIM];
__device__ float g_ca   [BB * NP * DIM];
__device__ float g_ffn  [BB * NP * DFF];
__device__ float g_track[BB * NT * DIM];
__device__ float g_qh   [BB * NP * DIM];
__device__ float g_kp   [BB * NP * DIM];
__device__ float g_kt   [BB * NT * DIM];
__device__ float g_qn   [BB * NP * NH2];
__device__ float g_kpn  [BB * NP * NH2];
__device__ float g_ktn  [BB * NT * NH2];

// ---------------- generic tiled SGEMM:  C = A(MxK) @ B(KxN) + bias, opt ReLU ----------------
// 64x64 tile, BK=16, 256 threads, 4x4 register micro-tile. Requires N % 64 == 0, K % 16 == 0.
template <bool RELU>
__global__ void sgemm_kernel(const float* __restrict__ A, const float* __restrict__ Bm,
                             const float* __restrict__ bias, float* __restrict__ C,
                             int M, int N, int K) {
    __shared__ float As[16][65];
    __shared__ float Bs[16][64];
    const int tid = threadIdx.x;
    const int tx = tid & 15, ty = tid >> 4;
    const int bm = blockIdx.x, bn = blockIdx.y;

    float acc[4][4] = {};

    const int ar = tid >> 2, ac = (tid & 3) * 4;     // A tile load: 64 rows x 16 cols
    const int br = tid >> 4, bc = (tid & 15) * 4;    // B tile load: 16 rows x 64 cols
    const int arow = bm * 64 + ar;
    const float* Aptr = A + (size_t)arow * K + ac;
    const float* Bptr = Bm + (size_t)br * N + bn * 64 + bc;

    for (int kt = 0; kt < K; kt += 16) {
        float4 av = make_float4(0.f, 0.f, 0.f, 0.f);
        if (arow < M) av = *(const float4*)(Aptr + kt);
        As[ac + 0][ar] = av.x; As[ac + 1][ar] = av.y;
        As[ac + 2][ar] = av.z; As[ac + 3][ar] = av.w;
        float4 bv = *(const float4*)(Bptr + (size_t)kt * N);
        *(float4*)&Bs[br][bc] = bv;
        __syncthreads();
        #pragma unroll
        for (int k = 0; k < 16; k++) {
            float a0 = As[k][ty * 4 + 0], a1 = As[k][ty * 4 + 1];
            float a2 = As[k][ty * 4 + 2], a3 = As[k][ty * 4 + 3];
            float b0 = Bs[k][tx * 4 + 0], b1 = Bs[k][tx * 4 + 1];
            float b2 = Bs[k][tx * 4 + 2], b3 = Bs[k][tx * 4 + 3];
            acc[0][0] += a0 * b0; acc[0][1] += a0 * b1; acc[0][2] += a0 * b2; acc[0][3] += a0 * b3;
            acc[1][0] += a1 * b0; acc[1][1] += a1 * b1; acc[1][2] += a1 * b2; acc[1][3] += a1 * b3;
            acc[2][0] += a2 * b0; acc[2][1] += a2 * b1; acc[2][2] += a2 * b2; acc[2][3] += a2 * b3;
            acc[3][0] += a3 * b0; acc[3][1] += a3 * b1; acc[3][2] += a3 * b2; acc[3][3] += a3 * b3;
        }
        __syncthreads();
    }
    #pragma unroll
    for (int i = 0; i < 4; i++) {
        int row = bm * 64 + ty * 4 + i;
        if (row < M) {
            #pragma unroll
            for (int j = 0; j < 4; j++) {
                int col = bn * 64 + tx * 4 + j;
                float v = acc[i][j] + bias[col];
                if (RELU) v = fmaxf(v, 0.f);
                C[(size_t)row * N + col] = v;
            }
        }
    }
}

// ---------------- misc kernels ----------------
__global__ void posemb_kernel(const float* __restrict__ refp, float* __restrict__ out) {
    int idx = blockIdx.x * blockDim.x + threadIdx.x;
    if (idx >= BB * NP * DIM) return;
    int d = idx & 255;
    int q = (idx >> 8) % NP;
    int b = idx / (256 * NP);
    int c = d >> 6;            // which coord (0..3)
    int r = d & 63;
    int j = r >> 1;
    float pos = refp[(b * NQT + q) * 4 + c];
    float t = powf(10000.0f, (float)j / 32.0f);
    float arg = pos * 6.2831853071795864f / t;
    out[idx] = (r & 1) ? cosf(arg) : sinf(arg);
}

__global__ void copy_rows_kernel(const float* __restrict__ src, float* __restrict__ dst,
                                 int rowoff, int nrows) {
    int idx = blockIdx.x * blockDim.x + threadIdx.x;
    int total = BB * nrows * DIM;
    if (idx >= total) return;
    int d = idx & 255;
    int r = (idx >> 8) % nrows;
    int b = idx / (256 * nrows);
    dst[idx] = src[((size_t)(b * NQT + rowoff + r)) * DIM + d];
}

__global__ void add_kernel(const float* __restrict__ a, const float* __restrict__ b,
                           float* __restrict__ o, int n) {
    int idx = blockIdx.x * blockDim.x + threadIdx.x;
    if (idx < n) o[idx] = a[idx] + b[idx];
}

__global__ void attn_softmax_kernel() {
    int idx = blockIdx.x * blockDim.x + threadIdx.x;   // BB*NP*HH
    if (idx >= BB * NP * HH) return;
    int h = idx & 7;
    int bq = idx >> 3;
    const float* in = g_alog + (size_t)bq * 128 + h * 16;
    float mx = -1e30f;
    #pragma unroll
    for (int j = 0; j < 16; j++) mx = fmaxf(mx, in[j]);
    float e[16], s = 0.f;
    #pragma unroll
    for (int j = 0; j < 16; j++) { e[j] = expf(in[j] - mx); s += e[j]; }
    float inv = 1.0f / s;
    float* o = g_attn + (size_t)bq * 128 + h * 16;
    #pragma unroll
    for (int j = 0; j < 16; j++) o[j] = e[j] * inv;
}

// Aggregating gather: for each (b,q,h) accumulate Σ coef * src_row (256-dim) and Σ coef.
// block = (b,q), warp = head, lanes cover 256 channels as 2x float4.
__global__ void gather2_kernel(const float* __restrict__ refp, const float* __restrict__ src) {
    int bq = blockIdx.x;
    int b = bq / NP, q = bq % NP;
    int h = threadIdx.x >> 5;
    int lane = threadIdx.x & 31;
    const float* r = refp + (size_t)(b * NQT + q) * 4;
    float rx = r[0], ry = r[1], rw = r[2], rh = r[3];
    const float* offp = g_off + (size_t)bq * 256;
    const float* attp = g_attn + (size_t)bq * 128;

    float4 a0 = make_float4(0.f, 0.f, 0.f, 0.f);
    float4 a1 = make_float4(0.f, 0.f, 0.f, 0.f);
    float csum = 0.f;

    #pragma unroll
    for (int l = 0; l < 4; l++) {
        int wl = c_wl[l], hl = c_hl[l], st = c_start[l];
        float wlf = (float)wl, hlf = (float)hl;
        const float4* base = (const float4*)(src + ((size_t)b * STOT + st) * DIM);
        #pragma unroll
        for (int p = 0; p < 4; p++) {
            int oi = ((h * 4 + l) * 4 + p) * 2;
            float ox = offp[oi], oy = offp[oi + 1];
            float a = attp[h * 16 + l * 4 + p];
            float x = (rx + ox * 0.125f * rw) * wlf - 0.5f;
            float y = (ry + oy * 0.125f * rh) * hlf - 0.5f;
            float x0 = floorf(x), y0 = floorf(y);
            float lx = x - x0, ly = y - y0;
            float wgt[4] = { (1.f - lx) * (1.f - ly), lx * (1.f - ly),
                             (1.f - lx) * ly,         lx * ly };
            float xs[4] = { x0, x0 + 1.f, x0, x0 + 1.f };
            float ys[4] = { y0, y0, y0 + 1.f, y0 + 1.f };
            #pragma unroll
            for (int c = 0; c < 4; c++) {
                float xi = xs[c], yi = ys[c];
                if (xi >= 0.f && xi <= wlf - 1.f && yi >= 0.f && yi <= hlf - 1.f) {
                    int xii = (int)xi, yii = (int)yi;
                    float coef = a * wgt[c];
                    const float4* rp = base + (size_t)(yii * wl + xii) * 64;
                    float4 v0 = rp[lane];
                    float4 v1 = rp[lane + 32];
                    a0.x += coef * v0.x; a0.y += coef * v0.y;
                    a0.z += coef * v0.z; a0.w += coef * v0.w;
                    a1.x += coef * v1.x; a1.y += coef * v1.y;
                    a1.z += coef * v1.z; a1.w += coef * v1.w;
                    csum += coef;
                }
            }
        }
    }
    float4* ag = (float4*)(g_agg + ((size_t)bq * HH + h) * DIM);
    ag[lane] = a0;
    ag[lane + 32] = a1;
    if (lane == 0) g_coef[bq * HH + h] = csum;
}

// Per-head projection: capre[bq][h*32+j] = agg[bq][h] . Wv[:, h*32+j] + coef[bq][h]*bv[h*32+j]
// grid = (cdiv(2400,64), 8 heads), 256 threads, tile M=64 N=32 K=16, 2x4 micro-tile.
__global__ void hproj_kernel(const float* __restrict__ Wv, const float* __restrict__ bv) {
    __shared__ float As[16][65];
    __shared__ float Bs[16][32];
    const int h = blockIdx.y;
    const int bm = blockIdx.x;
    const int tid = threadIdx.x;
    const int tx = tid & 7, ty = tid >> 3;
    float acc[2][4] = {};

    const int ar = tid >> 2, ac = (tid & 3) * 4;     // A: 64 rows x 16 k
    const int kr = tid >> 4, bc = (tid & 15) * 2;    // B: 16 k x 32 cols
    const int arow = bm * 64 + ar;

    for (int k0 = 0; k0 < DIM; k0 += 16) {
        float4 av = make_float4(0.f, 0.f, 0.f, 0.f);
        if (arow < BB * NP)
            av = *(const float4*)(g_agg + ((size_t)arow * HH + h) * DIM + k0 + ac);
        As[ac + 0][ar] = av.x; As[ac + 1][ar] = av.y;
        As[ac + 2][ar] = av.z; As[ac + 3][ar] = av.w;
        float2 bvv = *(const float2*)(Wv + (size_t)(k0 + kr) * DIM + h * 32 + bc);
        Bs[kr][bc] = bvv.x; Bs[kr][bc + 1] = bvv.y;
        __syncthreads();
        #pragma unroll
        for (int k = 0; k < 16; k++) {
            float x0 = As[k][ty * 2 + 0], x1 = As[k][ty * 2 + 1];
            float b0 = Bs[k][tx * 4 + 0], b1 = Bs[k][tx * 4 + 1];
            float b2 = Bs[k][tx * 4 + 2], b3 = Bs[k][tx * 4 + 3];
            acc[0][0] += x0 * b0; acc[0][1] += x0 * b1; acc[0][2] += x0 * b2; acc[0][3] += x0 * b3;
            acc[1][0] += x1 * b0; acc[1][1] += x1 * b1; acc[1][2] += x1 * b2; acc[1][3] += x1 * b3;
        }
        __syncthreads();
    }
    #pragma unroll
    for (int i = 0; i < 2; i++) {
        int row = bm * 64 + ty * 2 + i;
        if (row < BB * NP) {
            float cf = g_coef[row * HH + h];
            #pragma unroll
            for (int j = 0; j < 4; j++) {
                int col = h * 32 + tx * 4 + j;
                g_capre[(size_t)row * DIM + col] = acc[i][j] + cf * bv[col];
            }
        }
    }
}

// fused residual + layernorm (warp per row, in-place on g_prop)
__global__ void ln_kernel(const float* __restrict__ addv, const float* __restrict__ w,
                          const float* __restrict__ bia) {
    int row = blockIdx.x * 8 + (threadIdx.x >> 5);
    int lane = threadIdx.x & 31;
    if (row >= BB * NP) return;
    float x[8];
    float s = 0.f;
    #pragma unroll
    for (int i = 0; i < 8; i++) {
        int d = lane + 32 * i;
        x[i] = g_prop[(size_t)row * DIM + d] + addv[(size_t)row * DIM + d];
        s += x[i];
    }
    #pragma unroll
    for (int o = 16; o > 0; o >>= 1) s += __shfl_xor_sync(0xffffffff, s, o);
    float m = s / 256.0f;
    float v = 0.f;
    #pragma unroll
    for (int i = 0; i < 8; i++) { float dd = x[i] - m; v += dd * dd; }
    #pragma unroll
    for (int o = 16; o > 0; o >>= 1) v += __shfl_xor_sync(0xffffffff, v, o);
    v /= 256.0f;
    float inv = rsqrtf(v + 1e-5f);
    #pragma unroll
    for (int i = 0; i < 8; i++) {
        int d = lane + 32 * i;
        g_prop[(size_t)row * DIM + d] = (x[i] - m) * inv * w[d] + bia[d];
    }
}

// per (row, h2) L2 norm of a 128-dim half-row
__global__ void norm_kernel(const float* __restrict__ X, int rows, float* __restrict__ out) {
    int idx = blockIdx.x * blockDim.x + threadIdx.x;
    if (idx >= rows * NH2) return;
    int h = idx & 1, r = idx >> 1;
    const float* x = X + (size_t)r * DIM + h * DH2;
    float s = 0.f;
    #pragma unroll 8
    for (int d = 0; d < 128; d++) { float v = x[d]; s += v * v; }
    out[idx] = sqrtf(s);
}

// fused weight_attn:   dots + softmax(mm) + cosine.  grid = (NP, 2, B), 128 threads.
__global__ void wattn_kernel(const float* __restrict__ Q, const float* __restrict__ K,
                             const float* __restrict__ qn, const float* __restrict__ kn,
                             int nk, float* __restrict__ cos_out, float* __restrict__ mm_out) {
    int qi = blockIdx.x, h = blockIdx.y, b = blockIdx.z;
    __shared__ float qv[128];
    __shared__ float sc[304];
    __shared__ float red[128];
    int t = threadIdx.x;
    int qrow = b * NP + qi;
    qv[t] = Q[(size_t)qrow * DIM + h * DH2 + t];
    __syncthreads();
    for (int k = t; k < nk; k += 128) {
        const float* kr = K + ((size_t)(b * nk + k)) * DIM + h * DH2;
        float dot = 0.f;
        #pragma unroll 8
        for (int d = 0; d < 128; d++) dot += qv[d] * kr[d];
        sc[k] = dot;
    }
    __syncthreads();
    const float scale = 0.088388347648318447f;   // 1/sqrt(128)
    float mx = -1e30f;
    for (int k = t; k < nk; k += 128) mx = fmaxf(mx, sc[k] * scale);
    red[t] = mx; __syncthreads();
    for (int s = 64; s > 0; s >>= 1) { if (t < s) red[t] = fmaxf(red[t], red[t + s]); __syncthreads(); }
    mx = red[0]; __syncthreads();
    float sum = 0.f;
    for (int k = t; k < nk; k += 128) sum += expf(sc[k] * scale - mx);
    red[t] = sum; __syncthreads();
    for (int s = 64; s > 0; s >>= 1) { if (t < s) red[t] += red[t + s]; __syncthreads(); }
    sum = red[0];
    float inv = 1.0f / sum;
    float qnv = qn[qrow * NH2 + h] + 1e-6f;
    size_t base = ((size_t)(b * NH2 + h) * NP + qi) * nk;
    for (int k = t; k < nk; k += 128) {
        mm_out[base + k] = expf(sc[k] * scale - mx) * inv;
        float knv = kn[(b * nk + k) * NH2 + h] + 1e-6f;
        cos_out[base + k] = sc[k] / (qnv * knv);
    }
}

__global__ void copy_prop_out(float* __restrict__ out) {
    int idx = blockIdx.x * blockDim.x + threadIdx.x;
    if (idx < BB * NP * DIM) out[OUT_PROP + idx] = g_prop[idx];
}
__global__ void copy_pref_out(const float* __restrict__ refp, float* __restrict__ out) {
    int idx = blockIdx.x * blockDim.x + threadIdx.x;
    if (idx >= BB * NP * 4) return;
    int c = idx & 3;
    int q = (idx >> 2) % NP;
    int b = idx / (4 * NP);
    out[OUT_PREF + idx] = refp[((size_t)(b * NQT + q)) * 4 + c];
}

// ---------------- host orchestration ----------------
static inline int cdiv(int a, int b) { return (a + b - 1) / b; }

extern "C" void kernel_launch(void* const* d_in, const int* in_sizes, int n_in,
                              void* d_out, int out_size) {
    const float* tgt   = (const float*)d_in[0];
    const float* refp  = (const float*)d_in[1];
    const float* src   = (const float*)d_in[2];
    const float* Woff  = (const float*)d_in[7];
    const float* boff  = (const float*)d_in[8];
    const float* Wa    = (const float*)d_in[9];
    const float* ba    = (const float*)d_in[10];
    const float* Wv    = (const float*)d_in[11];
    const float* bv    = (const float*)d_in[12];
    const float* Wout  = (const float*)d_in[13];
    const float* bout  = (const float*)d_in[14];
    const float* Wl1   = (const float*)d_in[15];
    const float* bl1   = (const float*)d_in[16];
    const float* Wl2   = (const float*)d_in[17];
    const float* bl2   = (const float*)d_in[18];
    const float* Wq    = (const float*)d_in[19];
    const float* bq    = (const float*)d_in[20];
    const float* Wk    = (const float*)d_in[21];
    const float* bk    = (const float*)d_in[22];
    const float* n1w   = (const float*)d_in[23];
    const float* n1b   = (const float*)d_in[24];
    const float* n3w   = (const float*)d_in[25];
    const float* n3b   = (const float*)d_in[26];
    float* out = (float*)d_out;

    float *pprop, *pppos, *pq, *poff, *palog, *pca, *pffn, *ptrack;
    float *pqh, *pkp, *pkt, *pqn, *pkpn, *pktn, *pcapre;
    cudaGetSymbolAddress((void**)&pprop,  g_prop);
    cudaGetSymbolAddress((void**)&pppos,  g_ppos);
    cudaGetSymbolAddress((void**)&pq,     g_q);
    cudaGetSymbolAddress((void**)&poff,   g_off);
    cudaGetSymbolAddress((void**)&palog,  g_alog);
    cudaGetSymbolAddress((void**)&pcapre, g_capre);
    cudaGetSymbolAddress((void**)&pca,    g_ca);
    cudaGetSymbolAddress((void**)&pffn,   g_ffn);
    cudaGetSymbolAddress((void**)&ptrack, g_track);
    cudaGetSymbolAddress((void**)&pqh,    g_qh);
    cudaGetSymbolAddress((void**)&pkp,    g_kp);
    cudaGetSymbolAddress((void**)&pkt,    g_kt);
    cudaGetSymbolAddress((void**)&pqn,    g_qn);
    cudaGetSymbolAddress((void**)&pkpn,   g_kpn);
    cudaGetSymbolAddress((void**)&pktn,   g_ktn);

    auto gemm = [&](const float* A, const float* Bw, const float* bias, float* C,
                    int M, int N, int K, bool relu) {
        dim3 g(cdiv(M, 64), N / 64);
        if (relu) sgemm_kernel<true><<<g, 256>>>(A, Bw, bias, C, M, N, K);
        else      sgemm_kernel<false><<<g, 256>>>(A, Bw, bias, C, M, N, K);
    };

    const int NPROPS = BB * NP;        // 2400 proposal rows
    const int NEL = NPROPS * DIM;      // 614400

    copy_rows_kernel<<<cdiv(NEL, 256), 256>>>(tgt, pprop, 0, NP);
    copy_rows_kernel<<<cdiv(BB * NT * DIM, 256), 256>>>(tgt, ptrack, NP, NT);
    posemb_kernel<<<cdiv(NEL, 256), 256>>>(refp, pppos);

    for (int l = 0; l < NLAY; l++) {
        // q = proposals + pos
        add_kernel<<<cdiv(NEL, 256), 256>>>(pprop, pppos, pq, NEL);
        // offsets + attention logits
        gemm(pq, Woff + (size_t)l * DIM * 256, boff + l * 256, poff, NPROPS, 256, DIM, false);
        gemm(pq, Wa + (size_t)l * DIM * 128, ba + l * 128, palog, NPROPS, 128, DIM, false);
        attn_softmax_kernel<<<cdiv(BB * NP * HH, 256), 256>>>();
        // aggregate src rows with combined bilinear*attention coefficients
        gather2_kernel<<<BB * NP, 256>>>(refp, src);
        // per-head projection through Wv (+ coef-weighted bias)
        dim3 hg(cdiv(NPROPS, 64), HH);
        hproj_kernel<<<hg, 256>>>(Wv + (size_t)l * DIM * DIM, bv + l * DIM);
        // output projection
        gemm(pcapre, Wout + (size_t)l * DIM * DIM, bout + l * DIM, pca, NPROPS, DIM, DIM, false);
        // residual + LN1
        ln_kernel<<<cdiv(NPROPS, 8), 256>>>(pca, n1w + l * DIM, n1b + l * DIM);
        // FFN
        gemm(pprop, Wl1 + (size_t)l * DIM * DFF, bl1 + l * DFF, pffn, NPROPS, DFF, DIM, true);
        gemm(pffn, Wl2 + (size_t)l * DFF * DIM, bl2 + l * DIM, pca, NPROPS, DIM, DFF, false);
        // residual + LN3
        ln_kernel<<<cdiv(NPROPS, 8), 256>>>(pca, n3w + l * DIM, n3b + l * DIM);
    }

    // weight_attn only matters for the last layer's weights
    const int L = NLAY - 1;
    gemm(pprop,  Wq + (size_t)L * DIM * DIM, bq + L * DIM, pqh, NPROPS, DIM, DIM, false);
    gemm(pprop,  Wk + (size_t)L * DIM * DIM, bk + L * DIM, pkp, NPROPS, DIM, DIM, false);
    gemm(ptrack, Wk + (size_t)L * DIM * DIM, bk + L * DIM, pkt, BB * NT, DIM, DIM, false);
    norm_kernel<<<cdiv(NPROPS * NH2, 256), 256>>>(pqh, NPROPS, pqn);
    norm_kernel<<<cdiv(NPROPS * NH2, 256), 256>>>(pkp, NPROPS, pkpn);
    norm_kernel<<<cdiv(BB * NT * NH2, 256), 256>>>(pkt, BB * NT, pktn);

    dim3 wg(NP, NH2, BB);
    wattn_kernel<<<wg, 128>>>(pqh, pkt, pqn, pktn, NT, out + OUT_PTCOS, out + OUT_PTMM);
    wattn_kernel<<<wg, 128>>>(pqh, pkp, pqn, pkpn, NP, out + OUT_PPCOS, out + OUT_PPMM);

    copy_prop_out<<<cdiv(NEL, 256), 256>>>(out);
    copy_pref_out<<<cdiv(BB * NP * 4, 256), 256>>>(refp, out);
}